// round 6
// baseline (speedup 1.0000x reference)
#include <cuda_runtime.h>
#include <math.h>

#define NB   8
#define NT   500
#define NF   257
#define NC   8
#define NNUL 4
#define LOWF 5
#define HIGHF 70
#define NBAND (HIGHF-LOWF)          // 65
#define NREST (NF-NBAND)            // 192
#define DCF_SIZE (NB*NT*NF*NNUL)

#define OMA   0.65f
#define AOVER 0.53846156f           // a/(1-a)

typedef unsigned long long u64;

// ---------------- scratch (zero at start of every call; k3_fix re-zeroes) ---
__device__ float g_pre[NB*NT];
__device__ float g_aft[NB*NT*NNUL];

// ---------------- packed f32x2 helpers ---------------------------------------
__device__ __forceinline__ u64 pack2(float lo, float hi) {
    u64 r; asm("mov.b64 %0, {%1, %2};" : "=l"(r) : "f"(lo), "f"(hi)); return r;
}
__device__ __forceinline__ u64 dup2(float x) { return pack2(x, x); }
__device__ __forceinline__ void unpack2(u64 v, float& lo, float& hi) {
    asm("mov.b64 {%0, %1}, %2;" : "=f"(lo), "=f"(hi) : "l"(v));
}
__device__ __forceinline__ u64 fma2(u64 a, u64 b, u64 c) {
    u64 d; asm("fma.rn.f32x2 %0, %1, %2, %3;" : "=l"(d) : "l"(a), "l"(b), "l"(c)); return d;
}
__device__ __forceinline__ u64 mul2(u64 a, u64 b) {
    u64 d; asm("mul.rn.f32x2 %0, %1, %2;" : "=l"(d) : "l"(a), "l"(b)); return d;
}

// ---------------- packed weights ----------------------------------------------
struct WPack {
    u64 t2[8];        // (twr_c, twi_c)
    u64 n2[NNUL][8];  // (nwr_c, nwi_c)
};

__device__ __forceinline__ void load_w(const float* __restrict__ tw,
                                       const float* __restrict__ nw,
                                       int beam, int f, WPack& W) {
    const float* a = tw + ((beam*2 + 0)*NF + f)*NC;
    const float* b = tw + ((beam*2 + 1)*NF + f)*NC;
    float4 a0 = ((const float4*)a)[0], a1 = ((const float4*)a)[1];
    float4 b0 = ((const float4*)b)[0], b1 = ((const float4*)b)[1];
    W.t2[0]=pack2(a0.x,b0.x); W.t2[1]=pack2(a0.y,b0.y);
    W.t2[2]=pack2(a0.z,b0.z); W.t2[3]=pack2(a0.w,b0.w);
    W.t2[4]=pack2(a1.x,b1.x); W.t2[5]=pack2(a1.y,b1.y);
    W.t2[6]=pack2(a1.z,b1.z); W.t2[7]=pack2(a1.w,b1.w);
    #pragma unroll
    for (int n = 0; n < NNUL; n++) {
        const float* c = nw + (((beam*NNUL + n)*2 + 0)*NF + f)*NC;
        const float* d = nw + (((beam*NNUL + n)*2 + 1)*NF + f)*NC;
        float4 c0 = ((const float4*)c)[0], c1 = ((const float4*)c)[1];
        float4 d0 = ((const float4*)d)[0], d1 = ((const float4*)d)[1];
        W.n2[n][0]=pack2(c0.x,d0.x); W.n2[n][1]=pack2(c0.y,d0.y);
        W.n2[n][2]=pack2(c0.z,d0.z); W.n2[n][3]=pack2(c0.w,d0.w);
        W.n2[n][4]=pack2(c1.x,d1.x); W.n2[n][5]=pack2(c1.y,d1.y);
        W.n2[n][6]=pack2(c1.z,d1.z); W.n2[n][7]=pack2(c1.w,d1.w);
    }
}

// ---------------- one (b,f,t) point: packed dots -> u2[4] (pr,pi), u8 -------
__device__ __forceinline__ void point_u(const float* __restrict__ in,
                                        const WPack& W, int b, int f, int t,
                                        u64 u2[4], float& u8,
                                        float& trO, float& tiO) {
    const float* xrp = in + ((size_t)(b*NT + t)*2 + 0)*(NF*NC) + f*NC;
    const float* xip = in + ((size_t)(b*NT + t)*2 + 1)*(NF*NC) + f*NC;
    float xr[8], xi[8];
    {
        float4 v0 = ((const float4*)xrp)[0], v1 = ((const float4*)xrp)[1];
        float4 w0 = ((const float4*)xip)[0], w1 = ((const float4*)xip)[1];
        xr[0]=v0.x; xr[1]=v0.y; xr[2]=v0.z; xr[3]=v0.w;
        xr[4]=v1.x; xr[5]=v1.y; xr[6]=v1.z; xr[7]=v1.w;
        xi[0]=w0.x; xi[1]=w0.y; xi[2]=w0.z; xi[3]=w0.w;
        xi[4]=w1.x; xi[5]=w1.y; xi[6]=w1.z; xi[7]=w1.w;
    }
    u64 dxr[8], dxi[8];
    #pragma unroll
    for (int c = 0; c < 8; c++) { dxr[c] = dup2(xr[c]); dxi[c] = dup2(xi[c]); }

    // power: P = sum (xr_c, xi_c)^2, pw = (P.lo + P.hi)/8
    u64 P = 0ull;
    #pragma unroll
    for (int c = 0; c < 8; c++) { u64 x2 = pack2(xr[c], xi[c]); P = fma2(x2, x2, P); }
    float plo, phi_; unpack2(P, plo, phi_);
    u8 = OMA * ((plo + phi_) * 0.125f);

    // target: A = sum w2*xr, B = sum w2*xi ; tr = A.lo - B.hi ; ti = A.hi + B.lo
    u64 A = 0ull, B = 0ull;
    #pragma unroll
    for (int c = 0; c < 8; c++) { A = fma2(W.t2[c], dxr[c], A); B = fma2(W.t2[c], dxi[c], B); }
    float ar, ai, br, bi;
    unpack2(A, ar, ai); unpack2(B, br, bi);
    float tr = ar - bi, ti = ai + br;
    trO = tr; tiO = ti;

    u64 tt = pack2(tr, ti);
    u64 ts = pack2(ti, -tr);
    u64 oma2 = dup2(OMA);

    #pragma unroll
    for (int n = 0; n < NNUL; n++) {
        u64 An = 0ull, Bn = 0ull;
        #pragma unroll
        for (int c = 0; c < 8; c++) {
            An = fma2(W.n2[n][c], dxr[c], An);
            Bn = fma2(W.n2[n][c], dxi[c], Bn);
        }
        float cr, ci, dr, di;
        unpack2(An, cr, ci); unpack2(Bn, dr, di);
        float nr = cr - di, ni = ci + dr;
        // (pr, pi) = nr*(tr,ti) + ni*(ti,-tr)
        u64 p2 = fma2(dup2(nr), tt, mul2(dup2(ni), ts));
        if (t == 0)   // reference's t=0 quirk
            p2 = fma2(dup2(AOVER*ni), ts, p2);
        u2[n] = mul2(oma2, p2);
    }
}

// ---------------- packed decayed Kogge-Stone over 32 lanes -------------------
__device__ __forceinline__ void scan_pk(u64 u2[4], float& u8, int lane) {
    const float AJ[5] = {0.35f, 0.1225f, 0.01500625f, 2.25187539e-4f, 5.07094278e-8f};
    #pragma unroll
    for (int s = 0; s < 5; s++) {
        int d = 1 << s;
        u64 aj2 = dup2(AJ[s]);
        #pragma unroll
        for (int k = 0; k < 4; k++) {
            u64 v = __shfl_up_sync(0xffffffffu, u2[k], d);
            if (lane >= d) u2[k] = fma2(aj2, v, u2[k]);
        }
        float vs = __shfl_up_sync(0xffffffffu, u8, d);
        if (lane >= d) u8 = fmaf(AJ[s], vs, u8);
    }
}

// =================== main fused kernel (band / rest variants) ===============
// block = 4 warps = 4 f's sharing one t-chunk; 2 chunks per f.
template<bool BAND>
__global__ __launch_bounds__(128)
void k_main(const float* __restrict__ in, const int* __restrict__ beam_id,
            const float* __restrict__ tw, const float* __restrict__ nw,
            float* __restrict__ out) {
    __shared__ float4 q_s[4][32];
    __shared__ float2 tg_s[4][32];
    __shared__ int    fs_s[4];
    __shared__ int    fv_s[4];

    const int NG = BAND ? 17 : 48;
    int bi    = blockIdx.x;
    int fgrp  = bi % NG;
    int chunk = (bi / NG) & 1;
    int b     = bi / (NG*2);

    int tid = threadIdx.x, lane = tid & 31, w = tid >> 5;
    int fidx = fgrp*4 + w;
    int valid, f;
    if (BAND) { valid = fidx < NBAND;  f = LOWF + min(fidx, NBAND-1); }
    else      { valid = 1;             f = (fidx < LOWF) ? fidx : fidx + NBAND; }
    if (lane == 0) { fs_s[w] = f; fv_s[w] = valid; }

    int beam = beam_id[b];
    WPack W;
    load_w(tw, nw, beam, f, W);

    float pa  = exp2f((float)(lane+1) * -1.5145732f);   // a^(lane+1)
    u64  pa2  = dup2(pa);
    u64  c2[4] = {0ull,0ull,0ull,0ull};
    float c8 = 0.0f;

    int T0   = chunk ? 224 : 0;
    int nit  = chunk ? 9 : 8;

    for (int it = 0; it < nit; it++) {
        bool wr = !(chunk && it == 0);   // chunk-1 iter 0 is warmup (discard)
        int t  = T0 + it*32 + lane;
        int tc = min(t, NT-1);

        u64 u2[4]; float u8, tr, ti;
        point_u(in, W, b, f, tc, u2, u8, tr, ti);
        scan_pk(u2, u8, lane);

        u64 y2[4]; float y8;
        #pragma unroll
        for (int k = 0; k < 4; k++) y2[k] = fma2(pa2, c2[k], u2[k]);
        y8 = fmaf(pa, c8, u8);
        #pragma unroll
        for (int k = 0; k < 4; k++) c2[k] = __shfl_sync(0xffffffffu, y2[k], 31);
        c8 = __shfl_sync(0xffffffffu, y8, 31);

        if (!wr) continue;

        // epilogue
        float yr[4], yi[4];
        #pragma unroll
        for (int n = 0; n < 4; n++) unpack2(y2[n], yr[n], yi[n]);

        float rinv = __fdividef(1.0f, y8 + 1e-13f);
        float ph[4], q[4];
        #pragma unroll
        for (int n = 0; n < 4; n++) {
            ph[n] = sqrtf(fmaf(yr[n], yr[n], yi[n]*yi[n]));
            q[n]  = fminf(fmaxf(ph[n]*rinv, 0.01f), 1.0f);
        }

        if (BAND) {
            if (valid && t < NT) {
                atomicAdd(g_pre + b*NT + t, y8);
                float* aftp = g_aft + (b*NT + t)*NNUL;
                #pragma unroll
                for (int n = 0; n < 4; n++) atomicAdd(aftp + n, ph[n]);
            }
        } else {
            if (t > 0 && t < NT) {
                float pinv = __fdividef(1.0f, g_pre[b*NT + t] + 1e-10f);
                float4 af = ((const float4*)g_aft)[b*NT + t];
                q[0] = sqrtf(q[0] * fminf(fmaxf(af.x*pinv, 0.01f), 1.0f));
                q[1] = sqrtf(q[1] * fminf(fmaxf(af.y*pinv, 0.01f), 1.0f));
                q[2] = sqrtf(q[2] * fminf(fmaxf(af.z*pinv, 0.01f), 1.0f));
                q[3] = sqrtf(q[3] * fminf(fmaxf(af.w*pinv, 0.01f), 1.0f));
            }
        }

        q_s[w][lane]  = make_float4(q[0], q[1], q[2], q[3]);
        tg_s[w][lane] = make_float2(tr, ti);
        __syncthreads();

        // dcf store: thread = (t_local, fi); contiguous float4 per (t,f)
        {
            int tl = tid >> 2, fi = tid & 3;
            int ttt = T0 + it*32 + tl;
            if (fv_s[fi] && ttt < NT)
                *(float4*)(out + ((size_t)(b*NT + ttt)*NF + fs_s[fi])*4) = q_s[fi][tl];
        }
        // targ store
        {
            int p = tid >> 6, rem = tid & 63, tl2 = rem >> 1, f2 = (rem & 1)*2;
            int tt2 = T0 + it*32 + tl2;
            if (tt2 < NT) {
                size_t base = DCF_SIZE + ((size_t)(b*NT + tt2)*2 + p)*NF;
                #pragma unroll
                for (int h = 0; h < 2; h++) {
                    if (fv_s[f2+h]) {
                        float2 v = tg_s[f2+h][tl2];
                        out[base + fs_s[f2+h]] = p ? v.y : v.x;
                    }
                }
            }
        }
        __syncthreads();
    }
}

// =================== k3_fix: re-ratio band dcf + reset accumulators =========
__global__ __launch_bounds__(128)
void k3_fix(float* __restrict__ out) {
    __shared__ float pre_s[32];
    __shared__ float aft_s[32][4];

    int bi = blockIdx.x;
    int tg = bi & 15;                // 16 t-groups of 32
    int b  = bi >> 4;
    int t0 = tg * 32;
    int tid = threadIdx.x;

    // load band sums for this block's (b, t) range
    {
        int tl = tid >> 2, nn = tid & 3;
        int t = t0 + tl;
        if (t < NT) aft_s[tl][nn] = g_aft[(b*NT + t)*NNUL + nn];
        if (tid < 32) {
            int tt = t0 + tid;
            if (tt < NT) pre_s[tid] = g_pre[b*NT + tt];
        }
    }
    __syncthreads();
    // reset for next graph replay (this block owns these (b,t) exclusively)
    {
        int tl = tid >> 2, nn = tid & 3;
        int t = t0 + tl;
        if (t < NT) g_aft[(b*NT + t)*NNUL + nn] = 0.0f;
        if (tid < 32) {
            int tt = t0 + tid;
            if (tt < NT) g_pre[b*NT + tt] = 0.0f;
        }
    }

    int tl2 = tid & 31, fc = tid >> 5;
    int t = t0 + tl2;
    if (t >= NT || t == 0) return;   // t=0 dcf is final already

    float pinv = __fdividef(1.0f, pre_s[tl2] + 1e-10f);
    float rat[4];
    #pragma unroll
    for (int n = 0; n < 4; n++)
        rat[n] = fminf(fmaxf(aft_s[tl2][n]*pinv, 0.01f), 1.0f);

    #pragma unroll 4
    for (int k = 0; k < 17; k++) {
        int fx = fc + 4*k;
        if (fx < NBAND) {
            int f = LOWF + fx;
            float* p = out + ((size_t)(b*NT + t)*NF + f)*4;
            float4 q = *(float4*)p;
            q.x = sqrtf(q.x * rat[0]);
            q.y = sqrtf(q.y * rat[1]);
            q.z = sqrtf(q.z * rat[2]);
            q.w = sqrtf(q.w * rat[3]);
            *(float4*)p = q;
        }
    }
}

// =================== launcher ===============================================
extern "C" void kernel_launch(void* const* d_in, const int* in_sizes, int n_in,
                              void* d_out, int out_size) {
    const float* in      = (const float*)d_in[0];
    const int*   beam_id = (const int*)  d_in[1];
    const float* tw      = (const float*)d_in[2];
    const float* nw      = (const float*)d_in[3];
    float* out = (float*)d_out;

    k_main<true ><<<NB*17*2, 128>>>(in, beam_id, tw, nw, out);  // band f's
    k_main<false><<<NB*48*2, 128>>>(in, beam_id, tw, nw, out);  // rest f's
    k3_fix<<<NB*16, 128>>>(out);                                // ratio fix + reset
}

// round 7
// speedup vs baseline: 1.3302x; 1.3302x over previous
#include <cuda_runtime.h>
#include <math.h>

#define NB   8
#define NT   500
#define NF   257
#define NC   8
#define NNUL 4
#define LOWF 5
#define HIGHF 70
#define DCF_SIZE (NB*NT*NF*NNUL)

#define OMA   0.65f
#define AOVER 0.53846156f           // a/(1-a)

#define NFG   65                    // ceil(257/4) f-groups
#define NCHUNK 4                    // t chunks of 128

// ---------------- scratch (left zeroed by k_fix for next graph replay) ------
__device__ float g_pre[NB*NT];
__device__ float g_aft[NB*NT*NNUL];

// ---------------- decayed Kogge-Stone over 32 lanes --------------------------
__device__ __forceinline__ void scan9(float u[9], int lane) {
    const float AJ0=0.35f, AJ1=0.1225f, AJ2=0.01500625f,
                AJ3=2.25187539e-4f, AJ4=5.07094278e-8f;
    #pragma unroll
    for (int kk = 0; kk < 9; kk++) {
        float v;
        v = __shfl_up_sync(0xffffffffu, u[kk], 1);  if (lane>=1)  u[kk]=fmaf(AJ0,v,u[kk]);
        v = __shfl_up_sync(0xffffffffu, u[kk], 2);  if (lane>=2)  u[kk]=fmaf(AJ1,v,u[kk]);
        v = __shfl_up_sync(0xffffffffu, u[kk], 4);  if (lane>=4)  u[kk]=fmaf(AJ2,v,u[kk]);
        v = __shfl_up_sync(0xffffffffu, u[kk], 8);  if (lane>=8)  u[kk]=fmaf(AJ3,v,u[kk]);
        v = __shfl_up_sync(0xffffffffu, u[kk], 16); if (lane>=16) u[kk]=fmaf(AJ4,v,u[kk]);
    }
}

// =================== k_main: fused beamform + scan -> pre-ratio dcf + targ ==
// grid = (b*4 + chunk)*65 + fgrp ; block = 128 (4 warps = 4 consecutive f)
__global__ __launch_bounds__(128)
void k_main(const float* __restrict__ in, const int* __restrict__ beam_id,
            const float* __restrict__ tw, const float* __restrict__ nw,
            float* __restrict__ out) {
    __shared__ float  xs[32][68];     // staged input: [t_local][part*32 + (f_l*8+c)]
    __shared__ float  wsm[4][80];     // per-warp weights: [w][16 targ | 64 null]
    __shared__ float4 q_s[4][32];
    __shared__ float2 tg_s[4][32];
    __shared__ int    fs_s[4], fv_s[4];

    int bi    = blockIdx.x;
    int fgrp  = bi % NFG;
    int rem   = bi / NFG;
    int chunk = rem & 3;
    int b     = rem >> 2;

    int tid = threadIdx.x, lane = tid & 31, w = tid >> 5;
    int f0  = fgrp * 4;
    int fv  = (f0 + w) < NF;
    int f   = min(f0 + w, NF-1);
    int beam = beam_id[b];
    bool inb = fv && (f >= LOWF) && (f < HIGHF);

    if (lane == 0) { fs_s[w] = f; fv_s[w] = fv; }

    // ---- stage weights (once) ----
    if (lane < 16) {   // target: [part(2)][c(8)]
        int part = lane >> 3, c = lane & 7;
        wsm[w][part*8 + c] = tw[((beam*2 + part)*NF + f)*NC + c];
    }
    {   // nulls: 64 floats, 2 per lane
        #pragma unroll
        for (int h = 0; h < 2; h++) {
            int j = lane + h*32;            // ((n*2+ri)*8+c)
            int n = j >> 4, ri = (j >> 3) & 1, c = j & 7;
            wsm[w][16 + j] = nw[(((beam*NNUL + n)*2 + ri)*NF + f)*NC + c];
        }
    }
    __syncthreads();

    // target weights -> registers
    float twr[8], twi[8];
    {
        float4 a0 = *(float4*)&wsm[w][0], a1 = *(float4*)&wsm[w][4];
        float4 b0 = *(float4*)&wsm[w][8], b1 = *(float4*)&wsm[w][12];
        twr[0]=a0.x; twr[1]=a0.y; twr[2]=a0.z; twr[3]=a0.w;
        twr[4]=a1.x; twr[5]=a1.y; twr[6]=a1.z; twr[7]=a1.w;
        twi[0]=b0.x; twi[1]=b0.y; twi[2]=b0.z; twi[3]=b0.w;
        twi[4]=b1.x; twi[5]=b1.y; twi[6]=b1.z; twi[7]=b1.w;
    }

    float pa = exp2f((float)(lane+1) * -1.5145732f);   // a^(lane+1)
    float carry[9];
    #pragma unroll
    for (int k = 0; k < 9; k++) carry[k] = 0.0f;

    const int ROWLIM = NF*NC - 4;   // clamp staged loads within row
    int T0 = chunk * 128;
    int itstart = chunk ? -1 : 0;   // it = -1 is warmup (discard)

    for (int it = itstart; it < 4; it++) {
        int tbase = T0 + it*32;
        __syncthreads();            // xs reusable (readers of prev iter done)

        // ---- stage input: 64 segs of 128B (32 t x 2 parts) ----
        #pragma unroll
        for (int pass = 0; pass < 4; pass++) {
            int i   = pass*128 + tid;       // 0..511
            int seg = i >> 3;
            int tl  = seg >> 1, part = seg & 1, e = i & 7;
            int tg  = min(tbase + tl, NT-1);
            int col = min(f0*NC + e*4, ROWLIM);
            const float* p = in + ((size_t)(b*NT + tg)*2 + part)*(NF*NC) + col;
            *(float4*)&xs[tl][part*32 + e*4] = *(const float4*)p;
        }
        __syncthreads();

        // ---- beamform from smem ----
        float xr[8], xi[8];
        {
            float4 r0 = *(float4*)&xs[lane][w*8];
            float4 r1 = *(float4*)&xs[lane][w*8 + 4];
            float4 i0 = *(float4*)&xs[lane][32 + w*8];
            float4 i1 = *(float4*)&xs[lane][32 + w*8 + 4];
            xr[0]=r0.x; xr[1]=r0.y; xr[2]=r0.z; xr[3]=r0.w;
            xr[4]=r1.x; xr[5]=r1.y; xr[6]=r1.z; xr[7]=r1.w;
            xi[0]=i0.x; xi[1]=i0.y; xi[2]=i0.z; xi[3]=i0.w;
            xi[4]=i1.x; xi[5]=i1.y; xi[6]=i1.z; xi[7]=i1.w;
        }

        float tr=0.f, ti=0.f, pw=0.f;
        #pragma unroll
        for (int c = 0; c < 8; c++) {
            tr = fmaf(twr[c], xr[c], tr); tr = fmaf(-twi[c], xi[c], tr);
            ti = fmaf(twi[c], xr[c], ti); ti = fmaf( twr[c], xi[c], ti);
            pw = fmaf(xr[c], xr[c], pw);  pw = fmaf(xi[c], xi[c], pw);
        }
        pw *= 0.125f;

        int t  = tbase + lane;
        int tc = min(t, NT-1);
        float u[9];
        #pragma unroll
        for (int n = 0; n < NNUL; n++) {
            float nwr_[8], nwi_[8];
            {
                float4 c0 = *(float4*)&wsm[w][16 + n*16];
                float4 c1 = *(float4*)&wsm[w][16 + n*16 + 4];
                float4 d0 = *(float4*)&wsm[w][16 + n*16 + 8];
                float4 d1 = *(float4*)&wsm[w][16 + n*16 + 12];
                nwr_[0]=c0.x; nwr_[1]=c0.y; nwr_[2]=c0.z; nwr_[3]=c0.w;
                nwr_[4]=c1.x; nwr_[5]=c1.y; nwr_[6]=c1.z; nwr_[7]=c1.w;
                nwi_[0]=d0.x; nwi_[1]=d0.y; nwi_[2]=d0.z; nwi_[3]=d0.w;
                nwi_[4]=d1.x; nwi_[5]=d1.y; nwi_[6]=d1.z; nwi_[7]=d1.w;
            }
            float nr=0.f, ni=0.f;
            #pragma unroll
            for (int c = 0; c < 8; c++) {
                nr = fmaf(nwr_[c], xr[c], nr); nr = fmaf(-nwi_[c], xi[c], nr);
                ni = fmaf(nwi_[c], xr[c], ni); ni = fmaf( nwr_[c], xi[c], ni);
            }
            float pr = tr*nr + ti*ni;
            float pi = ti*nr - tr*ni;
            if (tc == 0) {   // reference's t=0 quirk (chunk 0, iter 0, lane 0)
                pr = fmaf( AOVER*ti, ni, pr);
                pi = fmaf(-AOVER*tr, ni, pi);
            }
            u[n]   = OMA*pr;
            u[4+n] = OMA*pi;
        }
        u[8] = OMA*pw;

        scan9(u, lane);
        float y[9];
        #pragma unroll
        for (int k = 0; k < 9; k++) y[k] = fmaf(pa, carry[k], u[k]);
        #pragma unroll
        for (int k = 0; k < 9; k++) carry[k] = __shfl_sync(0xffffffffu, y[k], 31);

        if (it < 0) continue;       // warmup iteration: block-uniform skip

        // ---- epilogue: pre-ratio q, band atomics, staged coalesced stores --
        float rinv = __fdividef(1.0f, y[8] + 1e-13f);
        float ph[4], q[4];
        #pragma unroll
        for (int n = 0; n < 4; n++) {
            ph[n] = sqrtf(fmaf(y[n], y[n], y[4+n]*y[4+n]));
            q[n]  = fminf(fmaxf(ph[n]*rinv, 0.01f), 1.0f);
        }
        if (inb && t < NT) {
            atomicAdd(g_pre + b*NT + t, y[8]);
            float* aftp = g_aft + (b*NT + t)*NNUL;
            #pragma unroll
            for (int n = 0; n < 4; n++) atomicAdd(aftp + n, ph[n]);
        }

        q_s[w][lane]  = make_float4(q[0], q[1], q[2], q[3]);
        tg_s[w][lane] = make_float2(tr, ti);
        __syncthreads();

        {   // dcf: thread = (t_local, fi) -> 64B contiguous runs
            int tl = tid >> 2, fi = tid & 3;
            int tt = tbase + tl;
            if (fv_s[fi] && tt < NT)
                *(float4*)(out + ((size_t)(b*NT + tt)*NF + fs_s[fi])*4) = q_s[fi][tl];
        }
        {   // targ: thread = (part, t_local, f-pair)
            int p = tid >> 6, r2 = tid & 63, tl2 = r2 >> 1, f2 = (r2 & 1)*2;
            int tt2 = tbase + tl2;
            if (tt2 < NT) {
                size_t base = DCF_SIZE + ((size_t)(b*NT + tt2)*2 + p)*NF;
                #pragma unroll
                for (int h = 0; h < 2; h++) {
                    if (fv_s[f2+h]) {
                        float2 v = tg_s[f2+h][tl2];
                        out[base + fs_s[f2+h]] = p ? v.y : v.x;
                    }
                }
            }
        }
    }
}

// =================== k_fix: apply ratio to all f (t>=1) + reset accums ======
// block = (b, t-tile of 32); exclusively owns its (b,t) range.
__global__ __launch_bounds__(256)
void k_fix(float* __restrict__ out) {
    __shared__ float rat_s[32][4];
    __shared__ float aft_s[32][4];
    __shared__ float pre_s[32];

    int bi = blockIdx.x;
    int tg = bi & 15;
    int b  = bi >> 4;
    int t0 = tg * 32;
    int tid = threadIdx.x;

    if (tid < 128) {
        int tl = tid >> 2, n = tid & 3;
        int t = t0 + tl;
        if (t < NT) {
            aft_s[tl][n] = g_aft[(b*NT + t)*NNUL + n];
            if (n == 0) pre_s[tl] = g_pre[b*NT + t];
        }
    }
    __syncthreads();
    if (tid < 128) {   // reset for next graph replay (exclusive ownership)
        int tl = tid >> 2, n = tid & 3;
        int t = t0 + tl;
        if (t < NT) {
            g_aft[(b*NT + t)*NNUL + n] = 0.0f;
            if (n == 0) g_pre[b*NT + t] = 0.0f;
            float pinv = __fdividef(1.0f, pre_s[tl] + 1e-10f);
            rat_s[tl][n] = fminf(fmaxf(aft_s[tl][n]*pinv, 0.01f), 1.0f);
        }
    }
    __syncthreads();

    #pragma unroll 4
    for (int idx = tid; idx < 32*NF; idx += 256) {
        int tl = idx / NF, fx = idx % NF;
        int t = t0 + tl;
        if (t >= NT || t == 0) continue;   // t=0 dcf has no ratio
        float* p = out + ((size_t)(b*NT + t)*NF + fx)*4;
        float4 q = *(float4*)p;
        q.x = sqrtf(q.x * rat_s[tl][0]);
        q.y = sqrtf(q.y * rat_s[tl][1]);
        q.z = sqrtf(q.z * rat_s[tl][2]);
        q.w = sqrtf(q.w * rat_s[tl][3]);
        *(float4*)p = q;
    }
}

// =================== launcher ===============================================
extern "C" void kernel_launch(void* const* d_in, const int* in_sizes, int n_in,
                              void* d_out, int out_size) {
    const float* in      = (const float*)d_in[0];
    const int*   beam_id = (const int*)  d_in[1];
    const float* tw      = (const float*)d_in[2];
    const float* nw      = (const float*)d_in[3];
    float* out = (float*)d_out;

    k_main<<<NB*NCHUNK*NFG, 128>>>(in, beam_id, tw, nw, out);
    k_fix<<<NB*16, 256>>>(out);
}

// round 8
// speedup vs baseline: 1.7416x; 1.3093x over previous
#include <cuda_runtime.h>
#include <math.h>

#define NB   8
#define NT   500
#define NF   257
#define NC   8
#define NNUL 4
#define LOWF 5
#define HIGHF 70
#define DCF_SIZE (NB*NT*NF*NNUL)

#define OMA   0.65f
#define AOVER 0.53846156f           // a/(1-a)

#define NFG   65                    // ceil(257/4) f-groups
#define NCHUNK 4                    // t chunks of 128

// ---------------- scratch (k_rat leaves accums zeroed for next replay) ------
__device__ float g_pre[NB*NT];
__device__ float g_aft[NB*NT*NNUL];
__device__ float g_rat[NB*NT*NNUL];

// ---------------- decayed Kogge-Stone over 32 lanes --------------------------
__device__ __forceinline__ void scan9(float u[9], int lane) {
    const float AJ0=0.35f, AJ1=0.1225f, AJ2=0.01500625f,
                AJ3=2.25187539e-4f, AJ4=5.07094278e-8f;
    #pragma unroll
    for (int kk = 0; kk < 9; kk++) {
        float v;
        v = __shfl_up_sync(0xffffffffu, u[kk], 1);  if (lane>=1)  u[kk]=fmaf(AJ0,v,u[kk]);
        v = __shfl_up_sync(0xffffffffu, u[kk], 2);  if (lane>=2)  u[kk]=fmaf(AJ1,v,u[kk]);
        v = __shfl_up_sync(0xffffffffu, u[kk], 4);  if (lane>=4)  u[kk]=fmaf(AJ2,v,u[kk]);
        v = __shfl_up_sync(0xffffffffu, u[kk], 8);  if (lane>=8)  u[kk]=fmaf(AJ3,v,u[kk]);
        v = __shfl_up_sync(0xffffffffu, u[kk], 16); if (lane>=16) u[kk]=fmaf(AJ4,v,u[kk]);
    }
}

// =================== k_main: fused beamform + scan -> pre-ratio dcf + targ ==
// grid = (b*4 + chunk)*65 + fgrp ; block = 128 (4 warps = 4 consecutive f)
__global__ __launch_bounds__(128)
void k_main(const float* __restrict__ in, const int* __restrict__ beam_id,
            const float* __restrict__ tw, const float* __restrict__ nw,
            float* __restrict__ out) {
    __shared__ float  xs[32][68];     // staged input: [t_local][part*32 + (f_l*8+c)]
    __shared__ float  wsm[4][80];     // per-warp weights: [w][16 targ | 64 null]
    __shared__ float4 q_s[4][32];
    __shared__ float2 tg_s[4][32];
    __shared__ int    fs_s[4], fv_s[4];

    int bi    = blockIdx.x;
    int fgrp  = bi % NFG;
    int rem   = bi / NFG;
    int chunk = rem & 3;
    int b     = rem >> 2;

    int tid = threadIdx.x, lane = tid & 31, w = tid >> 5;
    int f0  = fgrp * 4;
    int fv  = (f0 + w) < NF;
    int f   = min(f0 + w, NF-1);
    int beam = beam_id[b];
    bool inb = fv && (f >= LOWF) && (f < HIGHF);

    if (lane == 0) { fs_s[w] = f; fv_s[w] = fv; }

    // ---- stage weights (once) ----
    if (lane < 16) {   // target: [part(2)][c(8)]
        int part = lane >> 3, c = lane & 7;
        wsm[w][part*8 + c] = tw[((beam*2 + part)*NF + f)*NC + c];
    }
    {   // nulls: 64 floats, 2 per lane
        #pragma unroll
        for (int h = 0; h < 2; h++) {
            int j = lane + h*32;            // ((n*2+ri)*8+c)
            int n = j >> 4, ri = (j >> 3) & 1, c = j & 7;
            wsm[w][16 + j] = nw[(((beam*NNUL + n)*2 + ri)*NF + f)*NC + c];
        }
    }
    __syncthreads();

    // target weights -> registers
    float twr[8], twi[8];
    {
        float4 a0 = *(float4*)&wsm[w][0], a1 = *(float4*)&wsm[w][4];
        float4 b0 = *(float4*)&wsm[w][8], b1 = *(float4*)&wsm[w][12];
        twr[0]=a0.x; twr[1]=a0.y; twr[2]=a0.z; twr[3]=a0.w;
        twr[4]=a1.x; twr[5]=a1.y; twr[6]=a1.z; twr[7]=a1.w;
        twi[0]=b0.x; twi[1]=b0.y; twi[2]=b0.z; twi[3]=b0.w;
        twi[4]=b1.x; twi[5]=b1.y; twi[6]=b1.z; twi[7]=b1.w;
    }

    float pa = exp2f((float)(lane+1) * -1.5145732f);   // a^(lane+1)
    float carry[9];
    #pragma unroll
    for (int k = 0; k < 9; k++) carry[k] = 0.0f;

    const int ROWLIM = NF*NC - 4;   // clamp staged loads within row
    int T0 = chunk * 128;
    int itstart = chunk ? -1 : 0;   // it = -1 is warmup (discard)

    for (int it = itstart; it < 4; it++) {
        int tbase = T0 + it*32;
        __syncthreads();            // xs reusable (readers of prev iter done)

        // ---- stage input: 64 segs of 128B (32 t x 2 parts) ----
        #pragma unroll
        for (int pass = 0; pass < 4; pass++) {
            int i   = pass*128 + tid;       // 0..511
            int seg = i >> 3;
            int tl  = seg >> 1, part = seg & 1, e = i & 7;
            int tg  = min(tbase + tl, NT-1);
            int col = min(f0*NC + e*4, ROWLIM);
            const float* p = in + ((size_t)(b*NT + tg)*2 + part)*(NF*NC) + col;
            *(float4*)&xs[tl][part*32 + e*4] = *(const float4*)p;
        }
        __syncthreads();

        // ---- beamform from smem ----
        float xr[8], xi[8];
        {
            float4 r0 = *(float4*)&xs[lane][w*8];
            float4 r1 = *(float4*)&xs[lane][w*8 + 4];
            float4 i0 = *(float4*)&xs[lane][32 + w*8];
            float4 i1 = *(float4*)&xs[lane][32 + w*8 + 4];
            xr[0]=r0.x; xr[1]=r0.y; xr[2]=r0.z; xr[3]=r0.w;
            xr[4]=r1.x; xr[5]=r1.y; xr[6]=r1.z; xr[7]=r1.w;
            xi[0]=i0.x; xi[1]=i0.y; xi[2]=i0.z; xi[3]=i0.w;
            xi[4]=i1.x; xi[5]=i1.y; xi[6]=i1.z; xi[7]=i1.w;
        }

        float tr=0.f, ti=0.f, pw=0.f;
        #pragma unroll
        for (int c = 0; c < 8; c++) {
            tr = fmaf(twr[c], xr[c], tr); tr = fmaf(-twi[c], xi[c], tr);
            ti = fmaf(twi[c], xr[c], ti); ti = fmaf( twr[c], xi[c], ti);
            pw = fmaf(xr[c], xr[c], pw);  pw = fmaf(xi[c], xi[c], pw);
        }
        pw *= 0.125f;

        int t  = tbase + lane;
        int tc = min(t, NT-1);
        float u[9];
        #pragma unroll
        for (int n = 0; n < NNUL; n++) {
            float nwr_[8], nwi_[8];
            {
                float4 c0 = *(float4*)&wsm[w][16 + n*16];
                float4 c1 = *(float4*)&wsm[w][16 + n*16 + 4];
                float4 d0 = *(float4*)&wsm[w][16 + n*16 + 8];
                float4 d1 = *(float4*)&wsm[w][16 + n*16 + 12];
                nwr_[0]=c0.x; nwr_[1]=c0.y; nwr_[2]=c0.z; nwr_[3]=c0.w;
                nwr_[4]=c1.x; nwr_[5]=c1.y; nwr_[6]=c1.z; nwr_[7]=c1.w;
                nwi_[0]=d0.x; nwi_[1]=d0.y; nwi_[2]=d0.z; nwi_[3]=d0.w;
                nwi_[4]=d1.x; nwi_[5]=d1.y; nwi_[6]=d1.z; nwi_[7]=d1.w;
            }
            float nr=0.f, ni=0.f;
            #pragma unroll
            for (int c = 0; c < 8; c++) {
                nr = fmaf(nwr_[c], xr[c], nr); nr = fmaf(-nwi_[c], xi[c], nr);
                ni = fmaf(nwi_[c], xr[c], ni); ni = fmaf( nwr_[c], xi[c], ni);
            }
            float pr = tr*nr + ti*ni;
            float pi = ti*nr - tr*ni;
            if (tc == 0) {   // reference's t=0 quirk (chunk 0, iter 0, lane 0)
                pr = fmaf( AOVER*ti, ni, pr);
                pi = fmaf(-AOVER*tr, ni, pi);
            }
            u[n]   = OMA*pr;
            u[4+n] = OMA*pi;
        }
        u[8] = OMA*pw;

        scan9(u, lane);
        float y[9];
        #pragma unroll
        for (int k = 0; k < 9; k++) y[k] = fmaf(pa, carry[k], u[k]);
        #pragma unroll
        for (int k = 0; k < 9; k++) carry[k] = __shfl_sync(0xffffffffu, y[k], 31);

        if (it < 0) continue;       // warmup iteration: block-uniform skip

        // ---- epilogue: pre-ratio q, band atomics, staged coalesced stores --
        float rinv = __fdividef(1.0f, y[8] + 1e-13f);
        float ph[4], q[4];
        #pragma unroll
        for (int n = 0; n < 4; n++) {
            ph[n] = sqrtf(fmaf(y[n], y[n], y[4+n]*y[4+n]));
            q[n]  = fminf(fmaxf(ph[n]*rinv, 0.01f), 1.0f);
        }
        if (inb && t < NT) {
            atomicAdd(g_pre + b*NT + t, y[8]);
            float* aftp = g_aft + (b*NT + t)*NNUL;
            #pragma unroll
            for (int n = 0; n < 4; n++) atomicAdd(aftp + n, ph[n]);
        }

        q_s[w][lane]  = make_float4(q[0], q[1], q[2], q[3]);
        tg_s[w][lane] = make_float2(tr, ti);
        __syncthreads();

        {   // dcf: thread = (t_local, fi) -> 64B contiguous runs
            int tl = tid >> 2, fi = tid & 3;
            int tt = tbase + tl;
            if (fv_s[fi] && tt < NT)
                *(float4*)(out + ((size_t)(b*NT + tt)*NF + fs_s[fi])*4) = q_s[fi][tl];
        }
        {   // targ: thread = (part, t_local, f-pair)
            int p = tid >> 6, r2 = tid & 63, tl2 = r2 >> 1, f2 = (r2 & 1)*2;
            int tt2 = tbase + tl2;
            if (tt2 < NT) {
                size_t base = DCF_SIZE + ((size_t)(b*NT + tt2)*2 + p)*NF;
                #pragma unroll
                for (int h = 0; h < 2; h++) {
                    if (fv_s[f2+h]) {
                        float2 v = tg_s[f2+h][tl2];
                        out[base + fs_s[f2+h]] = p ? v.y : v.x;
                    }
                }
            }
        }
    }
}

// =================== k_rat: ratios + accumulator reset (1 thread per (b,t)) =
__global__ __launch_bounds__(256)
void k_rat(void) {
    int idx = blockIdx.x*256 + threadIdx.x;
    if (idx >= NB*NT) return;
    float pre = g_pre[idx];
    float4 af = ((const float4*)g_aft)[idx];
    float pinv = __fdividef(1.0f, pre + 1e-10f);
    float4 r;
    r.x = fminf(fmaxf(af.x*pinv, 0.01f), 1.0f);
    r.y = fminf(fmaxf(af.y*pinv, 0.01f), 1.0f);
    r.z = fminf(fmaxf(af.z*pinv, 0.01f), 1.0f);
    r.w = fminf(fmaxf(af.w*pinv, 0.01f), 1.0f);
    ((float4*)g_rat)[idx] = r;
    // reset for next graph replay (exclusive ownership)
    g_pre[idx] = 0.0f;
    ((float4*)g_aft)[idx] = make_float4(0.f, 0.f, 0.f, 0.f);
}

// =================== k_fix_flat: streaming ratio apply (t >= 1) =============
__global__ __launch_bounds__(256)
void k_fix_flat(float* __restrict__ out) {
    int idx = blockIdx.x*256 + threadIdx.x;     // one per (b,t,f)
    if (idx >= NB*NT*NF) return;
    int bt = idx / NF;
    int t  = bt % NT;
    if (t == 0) return;                          // t=0 dcf has no ratio
    float4 rat = ((const float4*)g_rat)[bt];
    float* p = out + (size_t)idx*4;
    float4 q = *(float4*)p;
    q.x = sqrtf(q.x * rat.x);
    q.y = sqrtf(q.y * rat.y);
    q.z = sqrtf(q.z * rat.z);
    q.w = sqrtf(q.w * rat.w);
    *(float4*)p = q;
}

// =================== launcher ===============================================
extern "C" void kernel_launch(void* const* d_in, const int* in_sizes, int n_in,
                              void* d_out, int out_size) {
    const float* in      = (const float*)d_in[0];
    const int*   beam_id = (const int*)  d_in[1];
    const float* tw      = (const float*)d_in[2];
    const float* nw      = (const float*)d_in[3];
    float* out = (float*)d_out;

    k_main<<<NB*NCHUNK*NFG, 128>>>(in, beam_id, tw, nw, out);
    k_rat<<<(NB*NT + 255)/256, 256>>>();
    k_fix_flat<<<(NB*NT*NF + 255)/256, 256>>>(out);
}